// round 11
// baseline (speedup 1.0000x reference)
#include <cuda_runtime.h>
#include <cuda_bf16.h>
#include <cstdint>
#include <math.h>

// HungarianMatcher cost matrix (v11: fat warps, TPT=8, 128-thread blocks).
//   u = head_q - head_t,  v = tip_q - tip_t   (packed f32x2 diffs)
//   C = 5*(|ux|+|uy|+|vx|+|vy|) + 2.5*(|wx|+|wy|) + cls[label_t],  w = u+v
//
// v11: 8 targets per thread / 128 threads per block. Halves per-element
// store-issue cost (2 STG.128 per warp-q for 256 elements) and per-element
// loop/LDS overhead; 8 independent element chains per lane cover FP latency.
// Write-back stores (R10: streaming hints neutral-to-worse).

#define QT 8          // queries per block
#define TPT 8         // targets per thread
#define MAXNC 16

typedef unsigned long long u64;

__device__ __forceinline__ u64 pk2(float lo, float hi) {
    u64 r; asm("mov.b64 %0, {%1, %2};" : "=l"(r) : "f"(lo), "f"(hi)); return r;
}
__device__ __forceinline__ void upk2(u64 v, float& lo, float& hi) {
    asm("mov.b64 {%0, %1}, %2;" : "=f"(lo), "=f"(hi) : "l"(v));
}
__device__ __forceinline__ u64 addx2(u64 a, u64 b) {
    u64 r; asm("add.rn.f32x2 %0, %1, %2;" : "=l"(r) : "l"(a), "l"(b)); return r;
}
__device__ __forceinline__ u64 mulx2(u64 a, u64 b) {
    u64 r; asm("mul.rn.f32x2 %0, %1, %2;" : "=l"(r) : "l"(a), "l"(b)); return r;
}

__global__ __launch_bounds__(128)
void matcher_fused(const float* __restrict__ logits,
                   const float* __restrict__ pscrews,
                   const int*   __restrict__ tlabels,
                   const float* __restrict__ tscrews,
                   float* __restrict__ out,
                   int N, int nc, int T) {
    __shared__ float s_cls[QT * MAXNC];
    __shared__ float s_q[QT * 4];

    int qbase = blockIdx.x * QT;
    int k = threadIdx.x;

    // ---- stage this block's query screws (one 128B load per block)
    if (k < QT * 4) {
        int q = qbase + (k >> 2);
        s_q[k] = (q < N) ? pscrews[(long long)q * 4 + (k & 3)] : 0.0f;
    }

    // ---- per-block focal class costs
    if (k >= 32 && k < 32 + QT * nc) {
        int kk = k - 32;
        int q = qbase + kk / nc;
        int c = kk % nc;
        float cost = 0.0f;
        if (q < N) {
            float l = logits[(long long)q * nc + c];
            float p = 1.0f / (1.0f + expf(-l));
            float pos = (1.0f - p) * (1.0f - p) * (-logf(p + 1e-8f));
            float neg = p * p * (-log1pf(-(p - 1e-8f)));
            cost = 2.0f * (pos - neg);
        }
        s_cls[kk] = cost;
    }

    // ---- load TPT targets into registers (negated), clamped tail overlap
    const u64 NEG1 = 0xBF800000BF800000ULL;  // {-1, -1}

    int t0 = threadIdx.x * TPT;
    if (t0 > T - TPT) t0 = T - TPT;          // requires T >= TPT

    u64 nth[TPT], ntt[TPT];
    bool lsel[TPT];
    #pragma unroll
    for (int j = 0; j < TPT; j++) {
        int tj = t0 + j;
        float4 s = reinterpret_cast<const float4*>(tscrews)[tj];
        nth[j] = mulx2(pk2(s.x, s.y), NEG1);
        ntt[j] = mulx2(pk2(s.z, s.w), NEG1);
        lsel[j] = (tlabels[tj] != 0);
    }
    __syncthreads();

    int qmax = N - qbase;                     // >=1; usually QT
    float* ptr = out + (long long)qbase * T + t0;

    #pragma unroll
    for (int q = 0; q < QT; q++) {
        if (q >= qmax) break;

        float4 qs = reinterpret_cast<const float4*>(s_q)[q];   // LDS.128 bcast
        u64 qh2 = pk2(qs.x, qs.y);
        u64 qt2 = pk2(qs.z, qs.w);

        float c0 = s_cls[q * nc + 0];
        float c1 = (nc > 1) ? s_cls[q * nc + 1] : c0;

        float r[TPT];
        #pragma unroll
        for (int j = 0; j < TPT; j++) {
            u64 u = addx2(qh2, nth[j]);      // head diff
            u64 v = addx2(qt2, ntt[j]);      // tip diff
            u64 w = addx2(u, v);             // 2*mid diff
            float ux, uy, vx, vy, wx, wy;
            upk2(u, ux, uy); upk2(v, vx, vy); upk2(w, wx, wy);
            float s1 = fabsf(ux) + fabsf(uy);    // FADD |a|,|b|
            float s2 = fabsf(vx) + fabsf(vy);
            float s3 = fabsf(wx) + fabsf(wy);
            float cls = lsel[j] ? c1 : c0;
            r[j] = fmaf(5.0f, s1 + s2, fmaf(2.5f, s3, cls));
        }

        float4 v0; v0.x = r[0]; v0.y = r[1]; v0.z = r[2]; v0.w = r[3];
        float4 v1; v1.x = r[4]; v1.y = r[5]; v1.z = r[6]; v1.w = r[7];
        *reinterpret_cast<float4*>(ptr)     = v0;   // write-back STG.128
        *reinterpret_cast<float4*>(ptr + 4) = v1;
        ptr += T;                                   // incremental addressing
    }
}

extern "C" void kernel_launch(void* const* d_in, const int* in_sizes, int n_in,
                              void* d_out, int out_size) {
    const float* logits  = (const float*)d_in[0];   // [bs, nq, nc]
    const float* pscrews = (const float*)d_in[1];   // [bs, nq, 4]
    const int*   tlabels = (const int*)d_in[2];     // [T]
    const float* tscrews = (const float*)d_in[3];   // [T, 4]
    // d_in[4] (num_targets_per_image) does not affect the flat [N, T] output.

    int N  = in_sizes[1] / 4;          // bs * nq
    int nc = in_sizes[0] / N;          // 2
    int T  = in_sizes[2];              // total targets
    float* out = (float*)d_out;

    int need = (T + TPT - 1) / TPT;    // threads needed to cover T
    int tpb = need > 128 ? ((need + 31) & ~31) : 128;
    if (tpb > 1024) tpb = 1024;

    int blocks = (N + QT - 1) / QT;
    matcher_fused<<<blocks, tpb>>>(logits, pscrews, tlabels, tscrews, out, N, nc, T);
}

// round 12
// speedup vs baseline: 1.7837x; 1.7837x over previous
#include <cuda_runtime.h>
#include <cuda_bf16.h>
#include <cstdint>
#include <math.h>

// HungarianMatcher cost matrix (v12 = v5 shape + QT=16, __stcs stores).
//   u = head_q - head_t,  v = tip_q - tip_t   (packed f32x2 diffs)
//   C = 5*(|ux|+|uy|+|vx|+|vy|) + 2.5*(|wx|+|wy|) + cls[label_t],  w = u+v
//
// Evidence so far: 40-reg / 256-thread / TPT=4 shape is the plateau optimum
// (TPT=8 -> 39us, reg-capped occ=8 -> 28us, TMA store -> 24.8us). __stcs
// beats write-back on harness-reported time (L2 dirty-flush bleeds into
// subsequent replays). This round only amortizes the per-block prologue 2x.

#define QT 16         // queries per block
#define TPT 4         // targets per thread
#define MAXNC 8

typedef unsigned long long u64;

__device__ __forceinline__ u64 pk2(float lo, float hi) {
    u64 r; asm("mov.b64 %0, {%1, %2};" : "=l"(r) : "f"(lo), "f"(hi)); return r;
}
__device__ __forceinline__ void upk2(u64 v, float& lo, float& hi) {
    asm("mov.b64 {%0, %1}, %2;" : "=f"(lo), "=f"(hi) : "l"(v));
}
__device__ __forceinline__ u64 addx2(u64 a, u64 b) {
    u64 r; asm("add.rn.f32x2 %0, %1, %2;" : "=l"(r) : "l"(a), "l"(b)); return r;
}
__device__ __forceinline__ u64 mulx2(u64 a, u64 b) {
    u64 r; asm("mul.rn.f32x2 %0, %1, %2;" : "=l"(r) : "l"(a), "l"(b)); return r;
}

__global__ __launch_bounds__(256)
void matcher_fused(const float* __restrict__ logits,
                   const float* __restrict__ pscrews,
                   const int*   __restrict__ tlabels,
                   const float* __restrict__ tscrews,
                   float* __restrict__ out,
                   int N, int nc, int T) {
    __shared__ float s_cls[QT * MAXNC];
    __shared__ float s_q[QT * 4];

    int qbase = blockIdx.x * QT;
    int k = threadIdx.x;

    // ---- stage this block's query screws (QT*4 = 64 floats)
    if (k < QT * 4) {
        int q = qbase + (k >> 2);
        s_q[k] = (q < N) ? pscrews[(long long)q * 4 + (k & 3)] : 0.0f;
    }

    // ---- per-block focal class costs (QT*nc = 32 threads for nc=2)
    if (k >= 64 && k < 64 + QT * nc) {
        int kk = k - 64;
        int q = qbase + kk / nc;
        int c = kk % nc;
        float cost = 0.0f;
        if (q < N) {
            float l = logits[(long long)q * nc + c];
            float p = 1.0f / (1.0f + expf(-l));
            float pos = (1.0f - p) * (1.0f - p) * (-logf(p + 1e-8f));
            float neg = p * p * (-log1pf(-(p - 1e-8f)));
            cost = 2.0f * (pos - neg);
        }
        s_cls[kk] = cost;
    }

    // ---- load TPT targets into registers (negated), clamped tail overlap
    const u64 NEG1 = 0xBF800000BF800000ULL;  // {-1, -1}

    int t0 = threadIdx.x * TPT;
    if (t0 > T - TPT) t0 = T - TPT;          // requires T >= TPT

    u64 nth[TPT], ntt[TPT];
    bool lsel[TPT];
    #pragma unroll
    for (int j = 0; j < TPT; j++) {
        int tj = t0 + j;
        float4 s = reinterpret_cast<const float4*>(tscrews)[tj];
        nth[j] = mulx2(pk2(s.x, s.y), NEG1);
        ntt[j] = mulx2(pk2(s.z, s.w), NEG1);
        lsel[j] = (tlabels[tj] != 0);
    }
    __syncthreads();

    int qmax = N - qbase;                     // >=1; usually QT
    float* ptr = out + (long long)qbase * T + t0;

    #pragma unroll
    for (int q = 0; q < QT; q++) {
        if (q >= qmax) break;

        float4 qs = reinterpret_cast<const float4*>(s_q)[q];   // LDS.128 bcast
        u64 qh2 = pk2(qs.x, qs.y);
        u64 qt2 = pk2(qs.z, qs.w);

        float c0 = s_cls[q * nc + 0];
        float c1 = (nc > 1) ? s_cls[q * nc + 1] : c0;

        float r[TPT];
        #pragma unroll
        for (int j = 0; j < TPT; j++) {
            u64 u = addx2(qh2, nth[j]);      // head diff
            u64 v = addx2(qt2, ntt[j]);      // tip diff
            u64 w = addx2(u, v);             // 2*mid diff
            float ux, uy, vx, vy, wx, wy;
            upk2(u, ux, uy); upk2(v, vx, vy); upk2(w, wx, wy);
            float s1 = fabsf(ux) + fabsf(uy);    // FADD |a|,|b|
            float s2 = fabsf(vx) + fabsf(vy);
            float s3 = fabsf(wx) + fabsf(wy);
            float cls = lsel[j] ? c1 : c0;
            r[j] = fmaf(5.0f, s1 + s2, fmaf(2.5f, s3, cls));
        }

        float4 vv; vv.x = r[0]; vv.y = r[1]; vv.z = r[2]; vv.w = r[3];
        __stcs(reinterpret_cast<float4*>(ptr), vv);
        ptr += T;                             // incremental addressing
    }
}

extern "C" void kernel_launch(void* const* d_in, const int* in_sizes, int n_in,
                              void* d_out, int out_size) {
    const float* logits  = (const float*)d_in[0];   // [bs, nq, nc]
    const float* pscrews = (const float*)d_in[1];   // [bs, nq, 4]
    const int*   tlabels = (const int*)d_in[2];     // [T]
    const float* tscrews = (const float*)d_in[3];   // [T, 4]
    // d_in[4] (num_targets_per_image) does not affect the flat [N, T] output.

    int N  = in_sizes[1] / 4;          // bs * nq
    int nc = in_sizes[0] / N;          // 2
    int T  = in_sizes[2];              // total targets
    float* out = (float*)d_out;

    int need = (T + TPT - 1) / TPT;    // threads needed to cover T
    int tpb = need > 256 ? ((need + 31) & ~31) : 256;
    if (tpb > 1024) tpb = 1024;

    int blocks = (N + QT - 1) / QT;
    matcher_fused<<<blocks, tpb>>>(logits, pscrews, tlabels, tscrews, out, N, nc, T);
}

// round 13
// speedup vs baseline: 1.8343x; 1.0283x over previous
#include <cuda_runtime.h>
#include <cuda_bf16.h>
#include <cstdint>
#include <math.h>

// HungarianMatcher cost matrix (v13 = v12 + QT=32 + clamped unconditional q-loop).
//   u = head_q - head_t,  v = tip_q - tip_t   (packed f32x2 diffs)
//   C = 5*(|ux|+|uy|+|vx|+|vy|) + 2.5*(|wx|+|wy|) + cls[label_t],  w = u+v
//
// Working lever (R12): amortize per-block prologue + per-q overhead at the
// fixed 40-reg / 256-thread / TPT=4 shape. QT=32 halves block count again;
// qbase clamping (like the target clamp) makes the q loop unconditional --
// overlapping blocks rewrite identical values (deterministic).

#define QT 32         // queries per block
#define TPT 4         // targets per thread
#define MAXNC 4

typedef unsigned long long u64;

__device__ __forceinline__ u64 pk2(float lo, float hi) {
    u64 r; asm("mov.b64 %0, {%1, %2};" : "=l"(r) : "f"(lo), "f"(hi)); return r;
}
__device__ __forceinline__ void upk2(u64 v, float& lo, float& hi) {
    asm("mov.b64 {%0, %1}, %2;" : "=f"(lo), "=f"(hi) : "l"(v));
}
__device__ __forceinline__ u64 addx2(u64 a, u64 b) {
    u64 r; asm("add.rn.f32x2 %0, %1, %2;" : "=l"(r) : "l"(a), "l"(b)); return r;
}
__device__ __forceinline__ u64 mulx2(u64 a, u64 b) {
    u64 r; asm("mul.rn.f32x2 %0, %1, %2;" : "=l"(r) : "l"(a), "l"(b)); return r;
}

__global__ __launch_bounds__(256)
void matcher_fused(const float* __restrict__ logits,
                   const float* __restrict__ pscrews,
                   const int*   __restrict__ tlabels,
                   const float* __restrict__ tscrews,
                   float* __restrict__ out,
                   int N, int nc, int T) {
    __shared__ float s_cls[QT * MAXNC];
    __shared__ float s_q[QT * 4];

    // clamp qbase so the q-loop is unconditional (requires N >= QT);
    // overlapping blocks redo identical work -> deterministic output.
    int qbase = blockIdx.x * QT;
    if (qbase > N - QT) qbase = N - QT;

    int k = threadIdx.x;

    // ---- stage this block's query screws (QT*4 = 128 floats)
    if (k < QT * 4) {
        int q = qbase + (k >> 2);
        s_q[k] = pscrews[(long long)q * 4 + (k & 3)];
    }

    // ---- per-block focal class costs (QT*nc = 64 lanes for nc=2)
    if (k >= 128 && k < 128 + QT * nc) {
        int kk = k - 128;
        int q = qbase + kk / nc;
        int c = kk % nc;
        float l = logits[(long long)q * nc + c];
        float p = 1.0f / (1.0f + expf(-l));
        float pos = (1.0f - p) * (1.0f - p) * (-logf(p + 1e-8f));
        float neg = p * p * (-log1pf(-(p - 1e-8f)));
        s_cls[kk] = 2.0f * (pos - neg);
    }

    // ---- load TPT targets into registers (negated), clamped tail overlap
    const u64 NEG1 = 0xBF800000BF800000ULL;  // {-1, -1}

    int t0 = threadIdx.x * TPT;
    if (t0 > T - TPT) t0 = T - TPT;          // requires T >= TPT

    u64 nth[TPT], ntt[TPT];
    bool lsel[TPT];
    #pragma unroll
    for (int j = 0; j < TPT; j++) {
        int tj = t0 + j;
        float4 s = reinterpret_cast<const float4*>(tscrews)[tj];
        nth[j] = mulx2(pk2(s.x, s.y), NEG1);
        ntt[j] = mulx2(pk2(s.z, s.w), NEG1);
        lsel[j] = (tlabels[tj] != 0);
    }
    __syncthreads();

    float* ptr = out + (long long)qbase * T + t0;

    #pragma unroll
    for (int q = 0; q < QT; q++) {
        float4 qs = reinterpret_cast<const float4*>(s_q)[q];   // LDS.128 bcast
        u64 qh2 = pk2(qs.x, qs.y);
        u64 qt2 = pk2(qs.z, qs.w);

        float c0 = s_cls[q * nc + 0];
        float c1 = (nc > 1) ? s_cls[q * nc + 1] : c0;

        float r[TPT];
        #pragma unroll
        for (int j = 0; j < TPT; j++) {
            u64 u = addx2(qh2, nth[j]);      // head diff
            u64 v = addx2(qt2, ntt[j]);      // tip diff
            u64 w = addx2(u, v);             // 2*mid diff
            float ux, uy, vx, vy, wx, wy;
            upk2(u, ux, uy); upk2(v, vx, vy); upk2(w, wx, wy);
            float s1 = fabsf(ux) + fabsf(uy);    // FADD |a|,|b|
            float s2 = fabsf(vx) + fabsf(vy);
            float s3 = fabsf(wx) + fabsf(wy);
            float cls = lsel[j] ? c1 : c0;
            r[j] = fmaf(5.0f, s1 + s2, fmaf(2.5f, s3, cls));
        }

        float4 vv; vv.x = r[0]; vv.y = r[1]; vv.z = r[2]; vv.w = r[3];
        __stcs(reinterpret_cast<float4*>(ptr), vv);
        ptr += T;                             // incremental addressing
    }
}

extern "C" void kernel_launch(void* const* d_in, const int* in_sizes, int n_in,
                              void* d_out, int out_size) {
    const float* logits  = (const float*)d_in[0];   // [bs, nq, nc]
    const float* pscrews = (const float*)d_in[1];   // [bs, nq, 4]
    const int*   tlabels = (const int*)d_in[2];     // [T]
    const float* tscrews = (const float*)d_in[3];   // [T, 4]
    // d_in[4] (num_targets_per_image) does not affect the flat [N, T] output.

    int N  = in_sizes[1] / 4;          // bs * nq
    int nc = in_sizes[0] / N;          // 2
    int T  = in_sizes[2];              // total targets
    float* out = (float*)d_out;

    int need = (T + TPT - 1) / TPT;    // threads needed to cover T
    int tpb = need > 256 ? ((need + 31) & ~31) : 256;
    if (tpb > 1024) tpb = 1024;

    int blocks = (N + QT - 1) / QT;
    matcher_fused<<<blocks, tpb>>>(logits, pscrews, tlabels, tscrews, out, N, nc, T);
}

// round 14
// speedup vs baseline: 1.9741x; 1.0762x over previous
#include <cuda_runtime.h>
#include <cuda_bf16.h>
#include <cstdint>
#include <math.h>

// HungarianMatcher cost matrix (v14 = v13 + FFMA-imm reduction chain).
//   u = head_q - head_t,  v = tip_q - tip_t   (packed f32x2 diffs)
//   C = 5*|u|_1 + 5*|v|_1 + 2.5*|u+v|_1 + cls[label_t]
//
// Reduction is a pure FFMA-immediate chain (rt_SMSP=1 per SASS_QUICKREF)
// instead of FADD (rt=2) + FFMA: fmaf(5,s1, fmaf(5,s2, fmaf(2.5,s3,cls))).
// Class costs fetched as one LDS.64 (float2). Shape fixed at the measured
// optimum: QT=32, TPT=4, 256 threads, ~40 regs, __stcs streaming stores.

#define QT 32         // queries per block
#define TPT 4         // targets per thread

typedef unsigned long long u64;

__device__ __forceinline__ u64 pk2(float lo, float hi) {
    u64 r; asm("mov.b64 %0, {%1, %2};" : "=l"(r) : "f"(lo), "f"(hi)); return r;
}
__device__ __forceinline__ void upk2(u64 v, float& lo, float& hi) {
    asm("mov.b64 {%0, %1}, %2;" : "=f"(lo), "=f"(hi) : "l"(v));
}
__device__ __forceinline__ u64 addx2(u64 a, u64 b) {
    u64 r; asm("add.rn.f32x2 %0, %1, %2;" : "=l"(r) : "l"(a), "l"(b)); return r;
}
__device__ __forceinline__ u64 mulx2(u64 a, u64 b) {
    u64 r; asm("mul.rn.f32x2 %0, %1, %2;" : "=l"(r) : "l"(a), "l"(b)); return r;
}

__global__ __launch_bounds__(256)
void matcher_fused(const float* __restrict__ logits,
                   const float* __restrict__ pscrews,
                   const int*   __restrict__ tlabels,
                   const float* __restrict__ tscrews,
                   float* __restrict__ out,
                   int N, int nc, int T) {
    __shared__ float2 s_cls[QT];             // {c0, c1} per query
    __shared__ float s_q[QT * 4];

    // clamp qbase so the q-loop is unconditional (requires N >= QT);
    // overlapping blocks redo identical work -> deterministic output.
    int qbase = blockIdx.x * QT;
    if (qbase > N - QT) qbase = N - QT;

    int k = threadIdx.x;

    // ---- stage this block's query screws (QT*4 = 128 floats)
    if (k < QT * 4) {
        int q = qbase + (k >> 2);
        s_q[k] = pscrews[(long long)q * 4 + (k & 3)];
    }

    // ---- per-block focal class costs (QT*nc lanes; nc<=2 packed as float2)
    if (k >= 128 && k < 128 + QT * nc) {
        int kk = k - 128;
        int q = qbase + kk / nc;
        int c = kk % nc;
        float l = logits[(long long)q * nc + c];
        float p = 1.0f / (1.0f + expf(-l));
        float pos = (1.0f - p) * (1.0f - p) * (-logf(p + 1e-8f));
        float neg = p * p * (-log1pf(-(p - 1e-8f)));
        float cost = 2.0f * (pos - neg);
        reinterpret_cast<float*>(s_cls)[kk / nc * 2 + c] = cost;
        if (nc == 1) reinterpret_cast<float*>(s_cls)[kk * 2 + 1] = cost;
    }

    // ---- load TPT targets into registers (negated), clamped tail overlap
    const u64 NEG1 = 0xBF800000BF800000ULL;  // {-1, -1}

    int t0 = threadIdx.x * TPT;
    if (t0 > T - TPT) t0 = T - TPT;          // requires T >= TPT

    u64 nth[TPT], ntt[TPT];
    bool lsel[TPT];
    #pragma unroll
    for (int j = 0; j < TPT; j++) {
        int tj = t0 + j;
        float4 s = reinterpret_cast<const float4*>(tscrews)[tj];
        nth[j] = mulx2(pk2(s.x, s.y), NEG1);
        ntt[j] = mulx2(pk2(s.z, s.w), NEG1);
        lsel[j] = (tlabels[tj] != 0);
    }
    __syncthreads();

    float* ptr = out + (long long)qbase * T + t0;

    #pragma unroll
    for (int q = 0; q < QT; q++) {
        float4 qs = reinterpret_cast<const float4*>(s_q)[q];   // LDS.128 bcast
        u64 qh2 = pk2(qs.x, qs.y);
        u64 qt2 = pk2(qs.z, qs.w);

        float2 cc = s_cls[q];                 // LDS.64 bcast: {c0, c1}

        float r[TPT];
        #pragma unroll
        for (int j = 0; j < TPT; j++) {
            u64 u = addx2(qh2, nth[j]);      // head diff
            u64 v = addx2(qt2, ntt[j]);      // tip diff
            u64 w = addx2(u, v);             // 2*mid diff
            float ux, uy, vx, vy, wx, wy;
            upk2(u, ux, uy); upk2(v, vx, vy); upk2(w, wx, wy);
            float s1 = fabsf(ux) + fabsf(uy);    // FADD |a|,|b|
            float s2 = fabsf(vx) + fabsf(vy);
            float s3 = fabsf(wx) + fabsf(wy);
            float cls = lsel[j] ? cc.y : cc.x;   // FSEL (alu pipe)
            // pure FFMA-immediate chain (rt=1 each)
            r[j] = fmaf(5.0f, s1, fmaf(5.0f, s2, fmaf(2.5f, s3, cls)));
        }

        float4 vv; vv.x = r[0]; vv.y = r[1]; vv.z = r[2]; vv.w = r[3];
        __stcs(reinterpret_cast<float4*>(ptr), vv);
        ptr += T;                             // incremental addressing
    }
}

extern "C" void kernel_launch(void* const* d_in, const int* in_sizes, int n_in,
                              void* d_out, int out_size) {
    const float* logits  = (const float*)d_in[0];   // [bs, nq, nc]
    const float* pscrews = (const float*)d_in[1];   // [bs, nq, 4]
    const int*   tlabels = (const int*)d_in[2];     // [T]
    const float* tscrews = (const float*)d_in[3];   // [T, 4]
    // d_in[4] (num_targets_per_image) does not affect the flat [N, T] output.

    int N  = in_sizes[1] / 4;          // bs * nq
    int nc = in_sizes[0] / N;          // 2
    int T  = in_sizes[2];              // total targets
    float* out = (float*)d_out;

    int need = (T + TPT - 1) / TPT;    // threads needed to cover T
    int tpb = need > 256 ? ((need + 31) & ~31) : 256;
    if (tpb > 1024) tpb = 1024;

    int blocks = (N + QT - 1) / QT;
    matcher_fused<<<blocks, tpb>>>(logits, pscrews, tlabels, tscrews, out, N, nc, T);
}